// round 1
// baseline (speedup 1.0000x reference)
#include <cuda_runtime.h>
#include <math.h>

#define BB 32
#define TT 256
#define EE 256
#define HH 512
#define G4 2048   // 4*HH
#define KK 20
#define START_TAG 18
#define END_TAG 19
#define NEGV (-10000.0f)

// ---------------- device-global scratch (no dynamic allocation) ----------------
__device__ float g_pre[(size_t)2 * TT * G4 * BB];     // [dir][t][gate][b]  128 MB
__device__ float g_h[2 * 2 * HH * BB];                // [dir][parity][j][b]
__device__ float g_c[2 * HH * BB];                    // [dir][j][b]
__device__ float g_lo[(size_t)BB * TT * 2 * HH];      // [b][t][2H] lstm concat out, 32 MB
__device__ float g_feats[(size_t)BB * TT * KK];       // [b][t][k]

// ---------------- init: zero LSTM states ----------------
__global__ void k_init() {
    int i = blockIdx.x * blockDim.x + threadIdx.x;
    if (i < 2 * 2 * HH * BB) g_h[i] = 0.0f;
    if (i < 2 * HH * BB) g_c[i] = 0.0f;
}

// ---------------- input-projection GEMM, embedding gather fused ----------------
// grid (TT, G4/64, 2), block 256.  out: g_pre[dir][t][g0..g0+63][b] = emb[tok]@W^T + bih
__global__ void __launch_bounds__(256) k_pregemm(
    const int* __restrict__ sent, const float* __restrict__ emb,
    const float* __restrict__ Wf, const float* __restrict__ Wb,
    const float* __restrict__ bf, const float* __restrict__ bb)
{
    extern __shared__ float sm[];
    float* xsT = sm;               // [256][33]  (e-major, padded)
    float* wsT = sm + 256 * 33;    // [256][68]  (e-major, padded, 16B-aligned rows)
    __shared__ int stok[BB];

    int t = blockIdx.x, gc = blockIdx.y, dir = blockIdx.z;
    int tid = threadIdx.x;
    if (tid < BB) stok[tid] = sent[tid * TT + t];
    __syncthreads();

    const float* W  = dir ? Wb : Wf;
    const float* bi = dir ? bb : bf;

    for (int i = tid; i < BB * EE; i += 256) {
        int b = i >> 8, e = i & 255;
        xsT[e * 33 + b] = emb[(size_t)stok[b] * EE + e];
    }
    int g0 = gc * 64;
    for (int i = tid; i < 64 * EE; i += 256) {
        int r = i >> 8, e = i & 255;
        wsT[e * 68 + r] = W[(size_t)(g0 + r) * EE + e];
    }
    __syncthreads();

    int tx = tid & 15, ty = tid >> 4;   // tx: batch pair, ty: gate quad
    int b0 = tx * 2;
    float a00 = 0.f, a01 = 0.f, a10 = 0.f, a11 = 0.f;
    float a20 = 0.f, a21 = 0.f, a30 = 0.f, a31 = 0.f;

#pragma unroll 4
    for (int k = 0; k < EE; k++) {
        float x0 = xsT[k * 33 + b0];
        float x1 = xsT[k * 33 + b0 + 1];
        float4 w = *(const float4*)&wsT[k * 68 + ty * 4];
        a00 = fmaf(w.x, x0, a00); a01 = fmaf(w.x, x1, a01);
        a10 = fmaf(w.y, x0, a10); a11 = fmaf(w.y, x1, a11);
        a20 = fmaf(w.z, x0, a20); a21 = fmaf(w.z, x1, a21);
        a30 = fmaf(w.w, x0, a30); a31 = fmaf(w.w, x1, a31);
    }

    size_t base = (((size_t)dir * TT + t) * G4 + g0) * BB;
    float acc[4][2] = {{a00,a01},{a10,a11},{a20,a21},{a30,a31}};
#pragma unroll
    for (int q = 0; q < 4; q++) {
        int g = ty * 4 + q;
        float bv = bi[g0 + g];
        float2 st = make_float2(acc[q][0] + bv, acc[q][1] + bv);
        *(float2*)&g_pre[base + (size_t)g * BB + b0] = st;
    }
}

// ---------------- one LSTM timestep, both directions fused ----------------
// grid 128 (0..63 fwd, 64..127 bwd), block 256 (8 warps), dyn smem HH*BB floats.
// warp -> hidden unit j, lane -> batch b.
__global__ void __launch_bounds__(256) k_step(
    int t,
    const float* __restrict__ Wfhh, const float* __restrict__ Wbhh,
    const float* __restrict__ bfhh, const float* __restrict__ bbhh,
    const int* __restrict__ lengths)
{
    extern __shared__ float sh[];   // h_prev in [k][b] layout
    int dir  = blockIdx.x >> 6;
    int jblk = blockIdx.x & 63;
    int warp = threadIdx.x >> 5, lane = threadIdx.x & 31;
    int par  = t & 1;

    const float* hsrc = g_h + (size_t)(dir * 2 + par) * HH * BB;
    for (int i = threadIdx.x; i < HH * BB; i += 256) sh[i] = hsrc[i];
    __syncthreads();

    int j = jblk * 8 + warp;
    const float* Whh = dir ? Wbhh : Wfhh;
    const float* bhh = dir ? bbhh : bfhh;
    int b = lane;

    // pack_padded reversal for backward dir (per-lane position)
    int pos = t;
    if (dir) { int len = lengths[b]; if (t < len) pos = len - 1 - t; }

    size_t preBase = (((size_t)dir * TT + pos) * G4) * BB + b;
    float zi = g_pre[preBase + (size_t)(0 * HH + j) * BB] + bhh[0 * HH + j];
    float zf = g_pre[preBase + (size_t)(1 * HH + j) * BB] + bhh[1 * HH + j];
    float zg = g_pre[preBase + (size_t)(2 * HH + j) * BB] + bhh[2 * HH + j];
    float zo = g_pre[preBase + (size_t)(3 * HH + j) * BB] + bhh[3 * HH + j];

    const float4* Wi = (const float4*)(Whh + (size_t)(0 * HH + j) * HH);
    const float4* Wf = (const float4*)(Whh + (size_t)(1 * HH + j) * HH);
    const float4* Wg = (const float4*)(Whh + (size_t)(2 * HH + j) * HH);
    const float4* Wo = (const float4*)(Whh + (size_t)(3 * HH + j) * HH);

#pragma unroll 4
    for (int kk = 0; kk < HH / 4; kk++) {
        float4 wi = Wi[kk], wf = Wf[kk], wg = Wg[kk], wo = Wo[kk];
        float h0 = sh[(kk * 4 + 0) * BB + lane];
        float h1 = sh[(kk * 4 + 1) * BB + lane];
        float h2 = sh[(kk * 4 + 2) * BB + lane];
        float h3 = sh[(kk * 4 + 3) * BB + lane];
        zi = fmaf(h0, wi.x, zi); zi = fmaf(h1, wi.y, zi); zi = fmaf(h2, wi.z, zi); zi = fmaf(h3, wi.w, zi);
        zf = fmaf(h0, wf.x, zf); zf = fmaf(h1, wf.y, zf); zf = fmaf(h2, wf.z, zf); zf = fmaf(h3, wf.w, zf);
        zg = fmaf(h0, wg.x, zg); zg = fmaf(h1, wg.y, zg); zg = fmaf(h2, wg.z, zg); zg = fmaf(h3, wg.w, zg);
        zo = fmaf(h0, wo.x, zo); zo = fmaf(h1, wo.y, zo); zo = fmaf(h2, wo.z, zo); zo = fmaf(h3, wo.w, zo);
    }

    float gi = 1.0f / (1.0f + expf(-zi));
    float gf = 1.0f / (1.0f + expf(-zf));
    float gg = 1.0f - 2.0f / (expf(2.0f * zg) + 1.0f);   // tanh
    float go = 1.0f / (1.0f + expf(-zo));

    float* cp = g_c + ((size_t)dir * HH + j) * BB + b;
    float c = gf * (*cp) + gi * gg;
    *cp = c;
    float h = go * (1.0f - 2.0f / (expf(2.0f * c) + 1.0f));

    g_h[((size_t)(dir * 2 + (par ^ 1)) * HH + j) * BB + b] = h;
    g_lo[((size_t)b * TT + pos) * (2 * HH) + (size_t)dir * HH + j] = h;
}

// ---------------- feats = lstm_out @ Wout^T + bout (masked by length) ----------------
// grid (8, 32): x = t-chunk of 32, y = batch.  dyn smem: WoutT [1024][20]
__global__ void __launch_bounds__(256) k_feats(
    const float* __restrict__ Wout, const float* __restrict__ bout,
    const int* __restrict__ lengths)
{
    extern __shared__ float WoT[];   // [2H][K]
    __shared__ float sb[KK];
    __shared__ int slen;
    int b = blockIdx.y, chunk = blockIdx.x;
    int tid = threadIdx.x;

    for (int i = tid; i < 2 * HH * KK; i += 256) {
        int k = i / (2 * HH), j = i % (2 * HH);
        WoT[j * KK + k] = Wout[(size_t)k * (2 * HH) + j];
    }
    if (tid < KK) sb[tid] = bout[tid];
    if (tid == 0) slen = lengths[b];
    __syncthreads();

    int len = slen;
    int t0 = chunk * 32;
    for (int p = tid; p < 32 * KK; p += 256) {
        int t = t0 + p / KK, k = p % KK;
        if (t >= len) continue;   // padded steps never read by viterbi
        const float* row = g_lo + ((size_t)b * TT + t) * (2 * HH);
        float acc = 0.0f;
#pragma unroll 8
        for (int j = 0; j < 2 * HH; j++)
            acc = fmaf(__ldg(&row[j]), WoT[j * KK + k], acc);
        g_feats[((size_t)b * TT + t) * KK + k] = acc + sb[k];
    }
}

// ---------------- Viterbi forward + backtrace, one warp per batch ----------------
__global__ void k_viterbi(const float* __restrict__ trans,
                          const int* __restrict__ lengths,
                          float* __restrict__ out)
{
    __shared__ unsigned char bp[TT][KK];
    int b = blockIdx.x;
    int nx = threadIdx.x;            // 0..31, tags are 0..19
    int len = lengths[b];

    float tr[KK];
#pragma unroll
    for (int p = 0; p < KK; p++) tr[p] = (nx < KK) ? trans[nx * KK + p] : 0.0f;

    float fv = (nx == START_TAG) ? 0.0f : NEGV;
    for (int t = 0; t < len; t++) {
        float best = -INFINITY; int barg = 0;
#pragma unroll
        for (int p = 0; p < KK; p++) {          // ascending + strict > == first-max (jnp.argmax)
            float fvp = __shfl_sync(0xffffffffu, fv, p);
            float s = fvp + tr[p];
            if (s > best) { best = s; barg = p; }
        }
        if (nx < KK) {
            bp[t][nx] = (unsigned char)barg;
            fv = best + g_feats[((size_t)b * TT + t) * KK + nx];
        } else {
            fv = NEGV;
        }
        __syncwarp();
    }

    float term = (nx < KK) ? (fv + trans[END_TAG * KK + nx]) : -INFINITY;
    float bestv = -INFINITY; int bt = 0;
#pragma unroll
    for (int p = 0; p < KK; p++) {
        float v = __shfl_sync(0xffffffffu, term, p);
        if (v > bestv) { bestv = v; bt = p; }
    }

    if (nx == 0) {
        out[b] = bestv;                                   // path_score [B,1]
        float* path = out + BB + (size_t)b * (TT + 1);    // best_path [B,T+1]
        path[TT] = (float)bt;
        int cur = bt;
        for (int i = 1; i <= len; i++) {
            cur = bp[len - i][cur];
            path[TT - i] = (float)cur;
        }
        for (int idx = 0; idx < TT - len; idx++) path[idx] = (float)KK;  // left pad sentinel
    }
}

// ---------------- launch ----------------
extern "C" void kernel_launch(void* const* d_in, const int* in_sizes, int n_in,
                              void* d_out, int out_size) {
    const int*   sent  = (const int*)d_in[0];
    const int*   lens  = (const int*)d_in[1];
    const float* emb   = (const float*)d_in[2];
    const float* Wf_ih = (const float*)d_in[3];
    const float* Wf_hh = (const float*)d_in[4];
    const float* bf_ih = (const float*)d_in[5];
    const float* bf_hh = (const float*)d_in[6];
    const float* Wb_ih = (const float*)d_in[7];
    const float* Wb_hh = (const float*)d_in[8];
    const float* bb_ih = (const float*)d_in[9];
    const float* bb_hh = (const float*)d_in[10];
    const float* Wout  = (const float*)d_in[11];
    const float* bout  = (const float*)d_in[12];
    const float* trans = (const float*)d_in[13];
    float* out = (float*)d_out;

    const int smem_pregemm = (256 * 33 + 256 * 68) * 4;   // ~103 KB
    const int smem_step    = HH * BB * 4;                 // 64 KB
    const int smem_feats   = 2 * HH * KK * 4;             // 80 KB
    cudaFuncSetAttribute(k_pregemm, cudaFuncAttributeMaxDynamicSharedMemorySize, smem_pregemm);
    cudaFuncSetAttribute(k_step,    cudaFuncAttributeMaxDynamicSharedMemorySize, smem_step);
    cudaFuncSetAttribute(k_feats,   cudaFuncAttributeMaxDynamicSharedMemorySize, smem_feats);

    k_init<<<(2 * 2 * HH * BB + 255) / 256, 256>>>();

    k_pregemm<<<dim3(TT, G4 / 64, 2), 256, smem_pregemm>>>(sent, emb, Wf_ih, Wb_ih, bf_ih, bb_ih);

    for (int t = 0; t < TT; t++)
        k_step<<<128, 256, smem_step>>>(t, Wf_hh, Wb_hh, bf_hh, bb_hh, lens);

    k_feats<<<dim3(8, BB), 256, smem_feats>>>(Wout, bout, lens);

    k_viterbi<<<BB, 32>>>(trans, lens, out);
}

// round 2
// speedup vs baseline: 1.7960x; 1.7960x over previous
#include <cuda_runtime.h>
#include <math.h>

#define BB 32
#define TT 256
#define EE 256
#define HH 512
#define G4 2048   // 4*HH
#define KK 20
#define START_TAG 18
#define END_TAG 19
#define NEGV (-10000.0f)
#define NBLK_DIR 64   // blocks per direction in k_lstm

// ---------------- device-global scratch (no dynamic allocation) ----------------
__device__ float g_pre[(size_t)2 * TT * G4 * BB];     // [dir][t][gate][b]  128 MB
__device__ float2 g_hp[2][2][256 * BB];               // [dir][buf][k2*BB+b] = (h[2k2],h[2k2+1])
__device__ float g_lo[(size_t)BB * TT * 2 * HH];      // [b][t][2H] lstm concat out
__device__ float g_feats[(size_t)BB * TT * KK];       // [b][t][k]
__device__ unsigned g_arrive[2];
__device__ unsigned g_release[2];

// ---------------- tiny helpers ----------------
__device__ __forceinline__ unsigned smem_u32(const void* p) {
    unsigned a;
    asm("{ .reg .u64 t; cvta.to.shared.u64 t, %1; cvt.u32.u64 %0, t; }" : "=r"(a) : "l"(p));
    return a;
}
__device__ __forceinline__ void fma2(unsigned long long& acc, unsigned long long a, unsigned long long b) {
    asm("fma.rn.f32x2 %0, %1, %2, %0;" : "+l"(acc) : "l"(a), "l"(b));
}
__device__ __forceinline__ void lds_v2u64(unsigned addr, unsigned long long& a, unsigned long long& b) {
    asm("ld.shared.v2.u64 {%0,%1}, [%2];" : "=l"(a), "=l"(b) : "r"(addr));
}
__device__ __forceinline__ unsigned long long lds_u64(unsigned addr) {
    unsigned long long v;
    asm("ld.shared.u64 %0, [%1];" : "=l"(v) : "r"(addr));
    return v;
}
__device__ __forceinline__ float hsum4(unsigned long long a, unsigned long long b) {
    float s = __uint_as_float((unsigned)a) + __uint_as_float((unsigned)(a >> 32));
    return s + __uint_as_float((unsigned)b) + __uint_as_float((unsigned)(b >> 32));
}

// ---------------- init: reset barrier state (must run every replay) ----------------
__global__ void k_init() {
    if (threadIdx.x < 2) { g_arrive[threadIdx.x] = 0u; g_release[threadIdx.x] = 0u; }
}

// ---------------- input-projection GEMM, embedding gather fused ----------------
__global__ void __launch_bounds__(256) k_pregemm(
    const int* __restrict__ sent, const float* __restrict__ emb,
    const float* __restrict__ Wf, const float* __restrict__ Wb,
    const float* __restrict__ bf, const float* __restrict__ bb)
{
    extern __shared__ float sm[];
    float* xsT = sm;               // [256][33]
    float* wsT = sm + 256 * 33;    // [256][68]
    __shared__ int stok[BB];

    int t = blockIdx.x, gc = blockIdx.y, dir = blockIdx.z;
    int tid = threadIdx.x;
    if (tid < BB) stok[tid] = sent[tid * TT + t];
    __syncthreads();

    const float* W  = dir ? Wb : Wf;
    const float* bi = dir ? bb : bf;

    for (int i = tid; i < BB * EE; i += 256) {
        int b = i >> 8, e = i & 255;
        xsT[e * 33 + b] = emb[(size_t)stok[b] * EE + e];
    }
    int g0 = gc * 64;
    for (int i = tid; i < 64 * EE; i += 256) {
        int r = i >> 8, e = i & 255;
        wsT[e * 68 + r] = W[(size_t)(g0 + r) * EE + e];
    }
    __syncthreads();

    int tx = tid & 15, ty = tid >> 4;
    int b0 = tx * 2;
    float a00 = 0.f, a01 = 0.f, a10 = 0.f, a11 = 0.f;
    float a20 = 0.f, a21 = 0.f, a30 = 0.f, a31 = 0.f;

#pragma unroll 4
    for (int k = 0; k < EE; k++) {
        float x0 = xsT[k * 33 + b0];
        float x1 = xsT[k * 33 + b0 + 1];
        float4 w = *(const float4*)&wsT[k * 68 + ty * 4];
        a00 = fmaf(w.x, x0, a00); a01 = fmaf(w.x, x1, a01);
        a10 = fmaf(w.y, x0, a10); a11 = fmaf(w.y, x1, a11);
        a20 = fmaf(w.z, x0, a20); a21 = fmaf(w.z, x1, a21);
        a30 = fmaf(w.w, x0, a30); a31 = fmaf(w.w, x1, a31);
    }

    size_t base = (((size_t)dir * TT + t) * G4 + g0) * BB;
    float acc[4][2] = {{a00,a01},{a10,a11},{a20,a21},{a30,a31}};
#pragma unroll
    for (int q = 0; q < 4; q++) {
        int g = ty * 4 + q;
        float bv = bi[g0 + g];
        float2 st = make_float2(acc[q][0] + bv, acc[q][1] + bv);
        *(float2*)&g_pre[base + (size_t)g * BB + b0] = st;
    }
}

// ---------------- persistent BiLSTM recurrence ----------------
// 128 blocks (0..63 fwd, 64..127 bwd), 256 threads (8 warps).  warp -> hidden j,
// lane -> batch b.  Weights in smem (loaded once), c in registers, h exchanged
// through L2 with a device-wide release/acquire barrier per timestep.
__global__ void __launch_bounds__(256) k_lstm(
    const float* __restrict__ Wfhh, const float* __restrict__ Wbhh,
    const float* __restrict__ bfhh, const float* __restrict__ bbhh,
    const int* __restrict__ lengths)
{
    extern __shared__ float sm[];
    float* sW = sm;          // [8 warps][4 gates][512]
    float* sh = sm + 16384;  // float2[256 pairs][32 b]

    const int dir  = (int)(blockIdx.x >> 6);
    const int jblk = (int)(blockIdx.x & 63);
    const int warp = threadIdx.x >> 5, lane = threadIdx.x & 31;
    const int j = jblk * 8 + warp;
    const float* __restrict__ Whh = dir ? Wbhh : Wfhh;
    const float* __restrict__ bhh = dir ? bbhh : bfhh;

    // load weights once: sW[wl][gate][k] = Whh[(gate*HH + jblk*8+wl)*HH + k]
    for (int i = threadIdx.x * 4; i < 16384; i += 1024) {
        int wl = i >> 11, gate = (i >> 9) & 3, k = i & 511;
        *(float4*)&sW[i] = *(const float4*)&Whh[((size_t)(gate * HH + jblk * 8 + wl)) * HH + k];
    }
    for (int i = threadIdx.x; i < HH * BB; i += 256) sh[i] = 0.0f;

    const float b_i = bhh[0 * HH + j];
    const float b_f = bhh[1 * HH + j];
    const float b_g = bhh[2 * HH + j];
    const float b_o = bhh[3 * HH + j];
    const int mylen = lengths[lane];
    float c = 0.0f;

    const unsigned smW = smem_u32(sW) + (unsigned)warp * 8192u;
    const unsigned smh = smem_u32(sh);
    __syncthreads();

    for (int t = 0; t < TT; t++) {
        if (t) {
            const float4* src = (const float4*)&g_hp[dir][t & 1][0];
            float4* dst = (float4*)sh;
#pragma unroll 4
            for (int i = threadIdx.x; i < 4096; i += 256) dst[i] = __ldcg(&src[i]);
            __syncthreads();
        }

        int pos = t;
        if (dir && t < mylen) pos = mylen - 1 - t;
        size_t preBase = (((size_t)dir * TT + pos) * G4) * BB + lane;
        float zi = g_pre[preBase + (size_t)(0 * HH + j) * BB] + b_i;
        float zf = g_pre[preBase + (size_t)(1 * HH + j) * BB] + b_f;
        float zg = g_pre[preBase + (size_t)(2 * HH + j) * BB] + b_g;
        float zo = g_pre[preBase + (size_t)(3 * HH + j) * BB] + b_o;

        unsigned long long ai0 = 0, ai1 = 0, af0 = 0, af1 = 0;
        unsigned long long ag0 = 0, ag1 = 0, ao0 = 0, ao1 = 0;
        unsigned hadr = smh + (unsigned)lane * 8u;

#pragma unroll 4
        for (int kq = 0; kq < 128; kq++) {
            unsigned long long wi0, wi1, wf0, wf1, wg0, wg1, wo0, wo1;
            unsigned wa = smW + (unsigned)kq * 16u;
            lds_v2u64(wa,          wi0, wi1);
            lds_v2u64(wa + 2048u,  wf0, wf1);
            lds_v2u64(wa + 4096u,  wg0, wg1);
            lds_v2u64(wa + 6144u,  wo0, wo1);
            unsigned long long h0 = lds_u64(hadr + (unsigned)kq * 512u);
            unsigned long long h1 = lds_u64(hadr + (unsigned)kq * 512u + 256u);
            fma2(ai0, wi0, h0); fma2(af0, wf0, h0); fma2(ag0, wg0, h0); fma2(ao0, wo0, h0);
            fma2(ai1, wi1, h1); fma2(af1, wf1, h1); fma2(ag1, wg1, h1); fma2(ao1, wo1, h1);
        }

        zi += hsum4(ai0, ai1);
        zf += hsum4(af0, af1);
        zg += hsum4(ag0, ag1);
        zo += hsum4(ao0, ao1);

        float gi = 1.0f / (1.0f + expf(-zi));
        float gf = 1.0f / (1.0f + expf(-zf));
        float gg = 1.0f - 2.0f / (expf(2.0f * zg) + 1.0f);
        float go = 1.0f / (1.0f + expf(-zo));

        c = gf * c + gi * gg;
        float h = go * (1.0f - 2.0f / (expf(2.0f * c) + 1.0f));

        // publish h (pair layout) + lstm output
        ((float*)&g_hp[dir][(t + 1) & 1][0])[((j >> 1) * BB + lane) * 2 + (j & 1)] = h;
        g_lo[((size_t)lane * TT + pos) * (2 * HH) + (size_t)dir * HH + j] = h;

        if (t < TT - 1) {
            __syncthreads();
            if (threadIdx.x == 0) {
                unsigned old;
                asm volatile("atom.release.gpu.global.add.u32 %0, [%1], %2;"
                             : "=r"(old) : "l"(&g_arrive[dir]), "r"(1u) : "memory");
                if (old == (unsigned)(NBLK_DIR * (t + 1) - 1)) {
                    asm volatile("st.release.gpu.global.u32 [%0], %1;"
                                 :: "l"(&g_release[dir]), "r"((unsigned)(t + 1)) : "memory");
                }
                unsigned r;
                do {
                    asm volatile("ld.acquire.gpu.global.u32 %0, [%1];"
                                 : "=r"(r) : "l"(&g_release[dir]) : "memory");
                } while (r < (unsigned)(t + 1));
            }
            __syncthreads();
        }
    }
}

// ---------------- feats = lstm_out @ Wout^T + bout (masked by length) ----------------
__global__ void __launch_bounds__(256) k_feats(
    const float* __restrict__ Wout, const float* __restrict__ bout,
    const int* __restrict__ lengths)
{
    extern __shared__ float WoT[];   // [2H][K]
    __shared__ float sb[KK];
    __shared__ int slen;
    int b = blockIdx.y, chunk = blockIdx.x;
    int tid = threadIdx.x;

    for (int i = tid; i < 2 * HH * KK; i += 256) {
        int k = i / (2 * HH), jj = i % (2 * HH);
        WoT[jj * KK + k] = Wout[(size_t)k * (2 * HH) + jj];
    }
    if (tid < KK) sb[tid] = bout[tid];
    if (tid == 0) slen = lengths[b];
    __syncthreads();

    int len = slen;
    int t0 = chunk * 32;
    for (int p = tid; p < 32 * KK; p += 256) {
        int t = t0 + p / KK, k = p % KK;
        if (t >= len) continue;
        const float* row = g_lo + ((size_t)b * TT + t) * (2 * HH);
        float acc = 0.0f;
#pragma unroll 8
        for (int jj = 0; jj < 2 * HH; jj++)
            acc = fmaf(__ldg(&row[jj]), WoT[jj * KK + k], acc);
        g_feats[((size_t)b * TT + t) * KK + k] = acc + sb[k];
    }
}

// ---------------- Viterbi forward + backtrace, one warp per batch ----------------
__global__ void k_viterbi(const float* __restrict__ trans,
                          const int* __restrict__ lengths,
                          float* __restrict__ out)
{
    __shared__ unsigned char bp[TT][KK];
    int b = blockIdx.x;
    int nx = threadIdx.x;
    int len = lengths[b];

    float tr[KK];
#pragma unroll
    for (int p = 0; p < KK; p++) tr[p] = (nx < KK) ? trans[nx * KK + p] : 0.0f;

    float fv = (nx == START_TAG) ? 0.0f : NEGV;
    for (int t = 0; t < len; t++) {
        float best = -INFINITY; int barg = 0;
#pragma unroll
        for (int p = 0; p < KK; p++) {
            float fvp = __shfl_sync(0xffffffffu, fv, p);
            float s = fvp + tr[p];
            if (s > best) { best = s; barg = p; }
        }
        if (nx < KK) {
            bp[t][nx] = (unsigned char)barg;
            fv = best + g_feats[((size_t)b * TT + t) * KK + nx];
        } else {
            fv = NEGV;
        }
        __syncwarp();
    }

    float term = (nx < KK) ? (fv + trans[END_TAG * KK + nx]) : -INFINITY;
    float bestv = -INFINITY; int bt = 0;
#pragma unroll
    for (int p = 0; p < KK; p++) {
        float v = __shfl_sync(0xffffffffu, term, p);
        if (v > bestv) { bestv = v; bt = p; }
    }

    if (nx == 0) {
        out[b] = bestv;
        float* path = out + BB + (size_t)b * (TT + 1);
        path[TT] = (float)bt;
        int cur = bt;
        for (int i = 1; i <= len; i++) {
            cur = bp[len - i][cur];
            path[TT - i] = (float)cur;
        }
        for (int idx = 0; idx < TT - len; idx++) path[idx] = (float)KK;
    }
}

// ---------------- launch ----------------
extern "C" void kernel_launch(void* const* d_in, const int* in_sizes, int n_in,
                              void* d_out, int out_size) {
    const int*   sent  = (const int*)d_in[0];
    const int*   lens  = (const int*)d_in[1];
    const float* emb   = (const float*)d_in[2];
    const float* Wf_ih = (const float*)d_in[3];
    const float* Wf_hh = (const float*)d_in[4];
    const float* bf_ih = (const float*)d_in[5];
    const float* bf_hh = (const float*)d_in[6];
    const float* Wb_ih = (const float*)d_in[7];
    const float* Wb_hh = (const float*)d_in[8];
    const float* bb_ih = (const float*)d_in[9];
    const float* bb_hh = (const float*)d_in[10];
    const float* Wout  = (const float*)d_in[11];
    const float* bout  = (const float*)d_in[12];
    const float* trans = (const float*)d_in[13];
    float* out = (float*)d_out;

    const int smem_pregemm = (256 * 33 + 256 * 68) * 4;
    const int smem_lstm    = 2 * 16384 * 4;               // 128 KB
    const int smem_feats   = 2 * HH * KK * 4;
    cudaFuncSetAttribute(k_pregemm, cudaFuncAttributeMaxDynamicSharedMemorySize, smem_pregemm);
    cudaFuncSetAttribute(k_lstm,    cudaFuncAttributeMaxDynamicSharedMemorySize, smem_lstm);
    cudaFuncSetAttribute(k_feats,   cudaFuncAttributeMaxDynamicSharedMemorySize, smem_feats);

    k_init<<<1, 32>>>();

    k_pregemm<<<dim3(TT, G4 / 64, 2), 256, smem_pregemm>>>(sent, emb, Wf_ih, Wb_ih, bf_ih, bb_ih);

    k_lstm<<<2 * NBLK_DIR, 256, smem_lstm>>>(Wf_hh, Wb_hh, bf_hh, bb_hh, lens);

    k_feats<<<dim3(8, BB), 256, smem_feats>>>(Wout, bout, lens);

    k_viterbi<<<BB, 32>>>(trans, lens, out);
}